// round 1
// baseline (speedup 1.0000x reference)
#include <cuda_runtime.h>
#include <cstdint>

// Problem constants: B=4, M_IN=16, M_OUT=32, C=32
// x: (4,16,32,32,32,32) fp32. out: (4,32,4,32) fp32.
//
// Math:
//   s1[b,m,c2] = sum over c3,c4,c5   (s2 == s1)
//   s3[b,m,c3] = sum over c2,c4,c5
//   s4[b,m,c4] = sum over c2,c3,c5
//   W[m,n] = alpha+beta+gamma+delta
//   out[b,n,i,c] = sum_m S_i[b,m,c] * W[m,n],  S = [s1,s1,s3,s4]

// -------- scratch (no allocations allowed) --------
__device__ float g_s1 [2048];        // [bid] where bid = (b*16+m)*32 + c2
__device__ float g_s3p[2048 * 32];   // [bid][c3]  (partial over c2)
__device__ float g_s4p[2048 * 32];   // [bid][c4]  (partial over c2)
__device__ float g_S  [8192];        // [b][m][i][c]

__device__ __forceinline__ unsigned long long addx2(unsigned long long a,
                                                    unsigned long long b) {
    unsigned long long r;
    asm("add.rn.f32x2 %0, %1, %2;" : "=l"(r) : "l"(a), "l"(b));
    return r;
}

__device__ __forceinline__ float x2sum(unsigned long long a) {
    unsigned lo, hi;
    asm("mov.b64 {%0,%1}, %2;" : "=r"(lo), "=r"(hi) : "l"(a));
    return __uint_as_float(lo) + __uint_as_float(hi);
}

// ---------------- Kernel 1: per-(b,m,c2) slice reduction ----------------
// Slice = 32768 contiguous floats (c3,c4,c5). 256 threads.
// float4 index q = k*256 + t  ->  c3 = k, c4 = t>>3, c5quad = t&7.
// Pass 1 (3 inst / 16B): LDG.128, add.rn.f32x2, STS.64 into sm[k][t].
// Pass 2: column sums -> s4 (c4 = t>>3 fixed per column-group of 8),
//         row sums    -> s3 (row k), s1 = sum_k s3[k].
__global__ void __launch_bounds__(256, 3)
k_reduce(const float* __restrict__ x) {
    extern __shared__ unsigned long long sm[];   // 32*256 = 64KB
    const int t   = threadIdx.x;
    const int bid = blockIdx.x;

    const ulonglong2* __restrict__ xv =
        reinterpret_cast<const ulonglong2*>(x + (size_t)bid * 32768);

    // ---- pass 1: stream 128KB, emit f32x2 partials ----
#pragma unroll
    for (int k = 0; k < 32; ++k) {
        ulonglong2 d = xv[k * 256 + t];          // LDG.128 (v.xy, v.zw packed)
        sm[k * 256 + t] = addx2(d.x, d.y);       // {x+z, y+w}
    }
    __syncthreads();

    const int lane = t & 31;
    const int warp = t >> 5;

    // ---- s4: column sums (c4 = t>>3 shared by 8 consecutive threads) ----
    unsigned long long c = sm[t];
#pragma unroll
    for (int k = 1; k < 32; ++k) c = addx2(c, sm[k * 256 + t]);
    float cs = x2sum(c);
    cs += __shfl_down_sync(0xffffffffu, cs, 4);
    cs += __shfl_down_sync(0xffffffffu, cs, 2);
    cs += __shfl_down_sync(0xffffffffu, cs, 1);
    if ((lane & 7) == 0) g_s4p[bid * 32 + (t >> 3)] = cs;

    // ---- s3: row sums; warp w handles rows k = 4w..4w+3 ----
    __shared__ float wt[8];
    float warp_tot = 0.f;
#pragma unroll
    for (int j = 0; j < 4; ++j) {
        const int k = warp * 4 + j;
        unsigned long long a = sm[k * 256 + lane];
#pragma unroll
        for (int i = 1; i < 8; ++i) a = addx2(a, sm[k * 256 + lane + i * 32]);
        float v = x2sum(a);
#pragma unroll
        for (int o = 16; o; o >>= 1) v += __shfl_down_sync(0xffffffffu, v, o);
        if (lane == 0) {
            g_s3p[bid * 32 + k] = v;
            warp_tot += v;
        }
    }
    if (lane == 0) wt[warp] = warp_tot;
    __syncthreads();
    if (t == 0) {
        float s = 0.f;
#pragma unroll
        for (int w = 0; w < 8; ++w) s += wt[w];
        g_s1[bid] = s;   // s1[b,m,c2] = slice total
    }
}

// ---------------- Kernel 2: assemble S[b][m][i][c] (8192 elems) ----------------
__global__ void __launch_bounds__(256)
k_assemble() {
    const int idx = blockIdx.x * 256 + threadIdx.x;   // 0..8191
    const int c  = idx & 31;
    const int i  = (idx >> 5) & 3;
    const int bm = idx >> 7;                          // 0..63
    float v;
    if (i < 2) {
        v = g_s1[bm * 32 + c];                        // c plays c2
    } else {
        const float* __restrict__ p = (i == 2 ? g_s3p : g_s4p) + bm * 1024 + c;
        v = 0.f;
#pragma unroll
        for (int c2 = 0; c2 < 32; ++c2) v += p[c2 * 32];
    }
    g_S[idx] = v;
}

// ---------------- Kernel 3: out[b,n,i,c] = sum_m S[b,m,i,c] * W[m,n] ----------------
__global__ void __launch_bounds__(256)
k_final(const float* __restrict__ a, const float* __restrict__ b,
        const float* __restrict__ g, const float* __restrict__ d,
        float* __restrict__ out) {
    __shared__ float W[512];                          // [m][n], 16x32
    const int t = threadIdx.x;
#pragma unroll
    for (int j = t; j < 512; j += 256) W[j] = a[j] + b[j] + g[j] + d[j];
    __syncthreads();

    const int idx = blockIdx.x * 256 + t;             // 0..16383
    const int c  = idx & 31;
    const int i  = (idx >> 5) & 3;
    const int n  = (idx >> 7) & 31;
    const int bb = idx >> 12;

    float acc = 0.f;
#pragma unroll
    for (int m = 0; m < 16; ++m)
        acc += g_S[((bb * 16 + m) * 4 + i) * 32 + c] * W[m * 32 + n];
    out[idx] = acc;
}

// ---------------- launch ----------------
extern "C" void kernel_launch(void* const* d_in, const int* in_sizes, int n_in,
                              void* d_out, int out_size) {
    const float* x     = (const float*)d_in[0];
    const float* alpha = (const float*)d_in[1];
    const float* beta  = (const float*)d_in[2];
    const float* gamma = (const float*)d_in[3];
    const float* delta = (const float*)d_in[4];

    // 64KB dynamic smem requires opting in past the 48KB default.
    // (Context-level call, not a stream op: legal under graph capture, idempotent.)
    cudaFuncSetAttribute(k_reduce, cudaFuncAttributeMaxDynamicSharedMemorySize, 65536);

    k_reduce  <<<2048, 256, 65536>>>(x);
    k_assemble<<<32,   256>>>();
    k_final   <<<64,   256>>>(alpha, beta, gamma, delta, (float*)d_out);
}